// round 1
// baseline (speedup 1.0000x reference)
#include <cuda_runtime.h>

// Problem constants (fixed by the reference)
#define BB 1024
#define NN 16
#define TT 256
#define NTRI (NN * (NN + 1) / 2)   // 136

// Scratch for deterministic two-pass reduction (no cudaMalloc allowed)
__device__ float g_partials[BB];

// One thread per (b, t). Block = 256 threads = one batch b, t = threadIdx.x.
// All cov loads are ((b*16+i)*16+j)*256 + t -> consecutive t across the warp
// -> perfectly coalesced 128B transactions. Only the lower triangle is read
// (cov is exactly symmetric by construction), saving 47% of cov traffic.
__global__ __launch_bounds__(TT) void gll_pair_kernel(
    const float* __restrict__ pred,
    const float* __restrict__ targ,
    const float* __restrict__ cov)
{
    const int b = blockIdx.x;
    const int t = threadIdx.x;

    // diff vector (becomes the forward-solve solution y in-place)
    float y[NN];
#pragma unroll
    for (int i = 0; i < NN; ++i) {
        const int off = (b * NN + i) * TT + t;
        y[i] = pred[off] - targ[off];
    }

    // Packed lower triangle of Sigma. Fully-unrolled indexing -> registers.
    float A[NTRI];
#pragma unroll
    for (int i = 0; i < NN; ++i) {
#pragma unroll
        for (int j = 0; j <= i; ++j) {
            A[i * (i + 1) / 2 + j] = cov[(((b * NN + i) * NN) + j) * TT + t];
        }
    }

    // Right-looking Cholesky, forward solve fused as augmented column.
    // Pivots >= lambda_min(Sigma) >= 1 (Sigma = A A^T + I), so log/rsqrt safe.
    float logdet = 0.0f;
    float quad   = 0.0f;
#pragma unroll
    for (int j = 0; j < NN; ++j) {
        const float s    = A[j * (j + 1) / 2 + j];   // pivot
        logdet += __logf(s);
        const float invd = rsqrtf(s);

        // scale column j and the augmented entry
        y[j] *= invd;
        quad = fmaf(y[j], y[j], quad);
#pragma unroll
        for (int i = j + 1; i < NN; ++i) {
            A[i * (i + 1) / 2 + j] *= invd;          // L[i][j]
        }
        // trailing update of the remaining lower triangle + augmented column
#pragma unroll
        for (int i = j + 1; i < NN; ++i) {
            const float lij = A[i * (i + 1) / 2 + j];
            y[i] = fmaf(-lij, y[j], y[i]);
#pragma unroll
            for (int k = j + 1; k <= i; ++k) {
                A[i * (i + 1) / 2 + k] =
                    fmaf(-lij, A[k * (k + 1) / 2 + j], A[i * (i + 1) / 2 + k]);
            }
        }
    }

    // Deterministic in-block tree reduction of quad + logdet
    __shared__ float red[TT];
    red[t] = quad + logdet;
    __syncthreads();
#pragma unroll
    for (int s = TT / 2; s > 0; s >>= 1) {
        if (t < s) red[t] += red[t + s];
        __syncthreads();
    }
    if (t == 0) g_partials[b] = red[0];
}

__global__ __launch_bounds__(256) void gll_reduce_kernel(float* __restrict__ out)
{
    __shared__ float red[256];
    float s = 0.0f;
#pragma unroll
    for (int i = threadIdx.x; i < BB; i += 256) s += g_partials[i];
    red[threadIdx.x] = s;
    __syncthreads();
#pragma unroll
    for (int k = 128; k > 0; k >>= 1) {
        if (threadIdx.x < k) red[threadIdx.x] += red[threadIdx.x + k];
        __syncthreads();
    }
    if (threadIdx.x == 0) out[0] = red[0] * (1.0f / (float)(BB * TT));
}

extern "C" void kernel_launch(void* const* d_in, const int* in_sizes, int n_in,
                              void* d_out, int out_size)
{
    const float* pred = (const float*)d_in[0];   // prediction [B,N,T]
    const float* targ = (const float*)d_in[1];   // target     [B,N,T]
    const float* cov  = (const float*)d_in[2];   // cov        [B,N,N,T]
    float* out = (float*)d_out;

    gll_pair_kernel<<<BB, TT>>>(pred, targ, cov);
    gll_reduce_kernel<<<1, 256>>>(out);
}

// round 2
// speedup vs baseline: 1.2713x; 1.2713x over previous
#include <cuda_runtime.h>

// Problem constants (fixed by the reference)
#define BB 1024
#define NN 16
#define TT 256
#define NTRI (NN * (NN + 1) / 2)   // 136
#define TPB 128                    // 128-thread blocks -> 3 CTAs/SM at ~170 regs
#define GRID (BB * TT / TPB)       // 2048 blocks, 2 per batch b

// Scratch for deterministic single-launch reduction (no cudaMalloc allowed)
__device__ float g_partials[GRID];
__device__ unsigned int g_count = 0;   // self-resetting arrival counter

// One thread per (b, t). Two blocks per b; t = (bid&1)*128 + tid.
// cov index ((b*16+i)*16+j)*256 + t -> consecutive t across the warp ->
// perfectly coalesced 128B transactions. Only the lower triangle is read
// (cov is exactly symmetric by construction): 136/256 planes = 47% less cov traffic.
__global__ __launch_bounds__(TPB) void gll_fused_kernel(
    const float* __restrict__ pred,
    const float* __restrict__ targ,
    const float* __restrict__ cov,
    float* __restrict__ out)
{
    const int bid = blockIdx.x;
    const int b   = bid >> 1;
    const int t   = ((bid & 1) << 7) + threadIdx.x;

    // diff vector (becomes the forward-solve solution y in-place)
    float y[NN];
#pragma unroll
    for (int i = 0; i < NN; ++i) {
        const int off = (b * NN + i) * TT + t;
        y[i] = pred[off] - targ[off];
    }

    // Packed lower triangle of Sigma. Fully-unrolled indexing -> registers.
    float A[NTRI];
#pragma unroll
    for (int i = 0; i < NN; ++i) {
#pragma unroll
        for (int j = 0; j <= i; ++j) {
            A[i * (i + 1) / 2 + j] = cov[(((b * NN + i) * NN) + j) * TT + t];
        }
    }

    // Right-looking Cholesky, forward solve fused as augmented column.
    // Pivots >= lambda_min(Sigma) >= 1 (Sigma = A A^T + I): log/rsqrt safe,
    // and the pivot product (~1e6 typical) stays comfortably in fp32 range,
    // so one __logf at the end replaces 16.
    float pivprod = 1.0f;
    float quad    = 0.0f;
#pragma unroll
    for (int j = 0; j < NN; ++j) {
        const float s    = A[j * (j + 1) / 2 + j];   // pivot
        pivprod *= s;
        const float invd = rsqrtf(s);

        // scale column j and the augmented entry
        y[j] *= invd;
        quad = fmaf(y[j], y[j], quad);
#pragma unroll
        for (int i = j + 1; i < NN; ++i) {
            A[i * (i + 1) / 2 + j] *= invd;          // L[i][j]
        }
        // trailing update of the remaining lower triangle + augmented column
#pragma unroll
        for (int i = j + 1; i < NN; ++i) {
            const float lij = A[i * (i + 1) / 2 + j];
            y[i] = fmaf(-lij, y[j], y[i]);
#pragma unroll
            for (int k = j + 1; k <= i; ++k) {
                A[i * (i + 1) / 2 + k] =
                    fmaf(-lij, A[k * (k + 1) / 2 + j], A[i * (i + 1) / 2 + k]);
            }
        }
    }

    float v = quad + __logf(pivprod);

    // In-block reduction: warp shuffles + one smem pass over 4 warps
    const int lane = threadIdx.x & 31;
    const int wid  = threadIdx.x >> 5;
#pragma unroll
    for (int o = 16; o > 0; o >>= 1) v += __shfl_down_sync(0xffffffffu, v, o);

    __shared__ float warpsum[TPB / 32];
    __shared__ bool  isLast;
    if (lane == 0) warpsum[wid] = v;
    __syncthreads();

    if (threadIdx.x == 0) {
        float s = warpsum[0] + warpsum[1] + warpsum[2] + warpsum[3];
        g_partials[bid] = s;
        __threadfence();
        unsigned int c = atomicAdd(&g_count, 1u);
        isLast = (c == (unsigned int)(GRID - 1));
    }
    __syncthreads();

    // Last arriving block performs the deterministic final sum (fixed order).
    if (isLast) {
        float s = 0.0f;
#pragma unroll 4
        for (int i = threadIdx.x; i < GRID; i += TPB) s += g_partials[i];
#pragma unroll
        for (int o = 16; o > 0; o >>= 1) s += __shfl_down_sync(0xffffffffu, s, o);
        if (lane == 0) warpsum[wid] = s;
        __syncthreads();
        if (threadIdx.x == 0) {
            float tot = warpsum[0] + warpsum[1] + warpsum[2] + warpsum[3];
            out[0] = tot * (1.0f / (float)(BB * TT));
            g_count = 0;   // reset for the next graph replay
        }
    }
}

extern "C" void kernel_launch(void* const* d_in, const int* in_sizes, int n_in,
                              void* d_out, int out_size)
{
    const float* pred = (const float*)d_in[0];   // prediction [B,N,T]
    const float* targ = (const float*)d_in[1];   // target     [B,N,T]
    const float* cov  = (const float*)d_in[2];   // cov        [B,N,N,T]
    float* out = (float*)d_out;

    gll_fused_kernel<<<GRID, TPB>>>(pred, targ, cov, out);
}